// round 2
// baseline (speedup 1.0000x reference)
#include <cuda_runtime.h>
#include <cuda_bf16.h>

// A = 8160 (68x120,s=8) + 2040 (34x60,s=16) + 510 (17x30,s=32) = 10710
// Output: [decoded B*A*16][fg B*A][ibc B*G*A], all f32.

#define A_TOTAL 10710
#define A_L0    8160
#define A_L01   10200
#define NB      32
#define NG      50
#define NCH     16

__device__ __forceinline__ void anchor_info(int a, int& level, float& xg, float& yg, float& s) {
    int i, w;
    if (a < A_L0)       { i = a;         w = 120; s = 8.0f;  level = 0; }
    else if (a < A_L01) { i = a - A_L0;  w = 60;  s = 16.0f; level = 1; }
    else                { i = a - A_L01; w = 30;  s = 32.0f; level = 2; }
    yg = (float)(i / w);
    xg = (float)(i % w);
}

__global__ __launch_bounds__(256)
void fused_decode_mask_kernel(const float* __restrict__ preds,
                              const float* __restrict__ labels,
                              float* __restrict__ out) {
    // Precomputed test bounds: box per g, ctr per (level, g).
    __shared__ float4 sbox[NG];
    __shared__ float4 sctr[3][NG];

    const int b   = blockIdx.y;
    const int tid = threadIdx.x;
    const float PINF = __int_as_float(0x7f800000);
    const float NINF = __int_as_float(0xff800000);

    if (tid < 3 * NG) {
        const int L = tid / NG;
        const int g = tid % NG;
        const float* lb = labels + ((size_t)b * NG + g) * 5;
        const float c  = lb[0];
        const float gx = lb[1];
        const float gy = lb[2];
        const float gw = lb[3];
        const float gh = lb[4];
        const bool valid = (c + gx + gy + gw + gh) > 0.0f;  // invalid rows are exactly 0
        if (L == 0) {
            const float hw = 0.5f * gw, hh = 0.5f * gh;
            sbox[g] = valid ? make_float4(gx - hw, gx + hw, gy - hh, gy + hh)
                            : make_float4(PINF, NINF, PINF, NINF);
        }
        const float r = (L == 0) ? 20.0f : (L == 1) ? 40.0f : 80.0f;  // 2.5 * stride
        sctr[L][g] = valid ? make_float4(gx - r, gx + r, gy - r, gy + r)
                           : make_float4(PINF, NINF, PINF, NINF);
    }
    __syncthreads();

    const int t  = blockIdx.x * blockDim.x + tid;
    const int a0 = t * 4;
    if (a0 >= A_TOTAL) return;
    const int nv = min(4, A_TOTAL - a0);

    float* out_fg  = out + (size_t)NB * A_TOTAL * NCH;
    float* out_ibc = out_fg + (size_t)NB * A_TOTAL;

    // ---- per-anchor centers + decode (contiguous 256B per thread) ----
    int level = 0;
    float xc[4], yc[4];
    for (int i = 0; i < nv; ++i) {
        const int a = a0 + i;
        int lv; float xg, yg, ss;
        anchor_info(a, lv, xg, yg, ss);
        level = lv;
        xc[i] = (xg + 0.5f) * ss;
        yc[i] = (yg + 0.5f) * ss;

        const float4* p4 = reinterpret_cast<const float4*>(
            preds + ((size_t)b * A_TOTAL + a) * NCH);
        float4* o4 = reinterpret_cast<float4*>(
            out + ((size_t)b * A_TOTAL + a) * NCH);
        float4 v0 = p4[0];
        float4 r0;
        r0.x = (v0.x + xg) * ss;
        r0.y = (v0.y + yg) * ss;
        r0.z = expf(v0.z) * ss;
        r0.w = expf(v0.w) * ss;
        o4[0] = r0;
        o4[1] = p4[1];
        o4[2] = p4[2];
        o4[3] = p4[3];
    }

    const float4* __restrict__ cb = sctr[level];
    float* ibc_base = out_ibc + (size_t)b * NG * A_TOTAL + a0;

    float mB[4], mC[4];
#pragma unroll
    for (int i = 0; i < 4; ++i) { mB[i] = NINF; mC[i] = NINF; }

    if (nv == 4) {
        // 4-anchor group never crosses a level boundary (8160, 10200 both % 4 == 0)
#pragma unroll 5
        for (int g = 0; g < NG; ++g) {
            const float4 Bx = sbox[g];
            const float4 Cx = cb[g];
            float w[4];
#pragma unroll
            for (int i = 0; i < 4; ++i) {
                const float mb = fminf(fminf(xc[i] - Bx.x, Bx.y - xc[i]),
                                       fminf(yc[i] - Bx.z, Bx.w - yc[i]));
                const float mc = fminf(fminf(xc[i] - Cx.x, Cx.y - xc[i]),
                                       fminf(yc[i] - Cx.z, Cx.w - yc[i]));
                mB[i] = fmaxf(mB[i], mb);
                mC[i] = fmaxf(mC[i], mc);
                // ibc = in_box & in_ctr  (the "& fg" in the reference is redundant:
                //  box&ctr true at (g,a) implies box|ctr true -> fg[a] true)
                w[i] = (fminf(mb, mc) > 0.0f) ? 1.0f : 0.0f;
            }
            float* p = ibc_base + (size_t)g * A_TOTAL;
            // A_TOTAL % 4 == 2 -> only 8B alignment guaranteed: use float2
            reinterpret_cast<float2*>(p)[0] = make_float2(w[0], w[1]);
            reinterpret_cast<float2*>(p)[1] = make_float2(w[2], w[3]);
        }
        float f[4];
#pragma unroll
        for (int i = 0; i < 4; ++i)
            f[i] = (fmaxf(mB[i], mC[i]) > 0.0f) ? 1.0f : 0.0f;
        float* pf = out_fg + (size_t)b * A_TOTAL + a0;
        reinterpret_cast<float2*>(pf)[0] = make_float2(f[0], f[1]);
        reinterpret_cast<float2*>(pf)[1] = make_float2(f[2], f[3]);
    } else {
        // tail: last group of a batch (2 anchors), scalar stores
        for (int g = 0; g < NG; ++g) {
            const float4 Bx = sbox[g];
            const float4 Cx = cb[g];
            float* p = ibc_base + (size_t)g * A_TOTAL;
            for (int i = 0; i < nv; ++i) {
                const float mb = fminf(fminf(xc[i] - Bx.x, Bx.y - xc[i]),
                                       fminf(yc[i] - Bx.z, Bx.w - yc[i]));
                const float mc = fminf(fminf(xc[i] - Cx.x, Cx.y - xc[i]),
                                       fminf(yc[i] - Cx.z, Cx.w - yc[i]));
                mB[i] = fmaxf(mB[i], mb);
                mC[i] = fmaxf(mC[i], mc);
                p[i] = (fminf(mb, mc) > 0.0f) ? 1.0f : 0.0f;
            }
        }
        float* pf = out_fg + (size_t)b * A_TOTAL + a0;
        for (int i = 0; i < nv; ++i)
            pf[i] = (fmaxf(mB[i], mC[i]) > 0.0f) ? 1.0f : 0.0f;
    }
}

extern "C" void kernel_launch(void* const* d_in, const int* in_sizes, int n_in,
                              void* d_out, int out_size) {
    const float* preds  = (const float*)d_in[0];
    const float* labels = (const float*)d_in[1];
    float* out = (float*)d_out;

    const int threads_per_batch = (A_TOTAL + 3) / 4;           // 2678
    dim3 block(256);
    dim3 grid((threads_per_batch + 255) / 256, NB);            // 11 x 32
    fused_decode_mask_kernel<<<grid, block>>>(preds, labels, out);
}

// round 5
// speedup vs baseline: 1.1379x; 1.1379x over previous
#include <cuda_runtime.h>
#include <cuda_bf16.h>

// A = 8160 (68x120,s=8) + 2040 (34x60,s=16) + 510 (17x30,s=32) = 10710
// Output: [decoded B*A*16][fg B*A][ibc B*G*A], all f32.
//
// Key identity: in_box(a,g) = min(xc-xlo, xhi-xc, yc-ylo, yhi-yc) > 0
//             = (min(xc-xlo, xhi-xc) > 0) AND (min(yc-ylo, yhi-yc) > 0)
// x-part depends only on the anchor's column (210 distinct values over 3 levels),
// y-part only on its row (119 distinct). Precompute 50-bit masks per column/row,
// then per anchor it's just 64-bit ANDs.

#define A_TOTAL 10710
#define A_L0    8160
#define A_L01   10200
#define NB      32
#define NG      50
#define NCH     16

#define NCOLS   210   // 120 + 60 + 30
#define NROWS   119   // 68 + 34 + 17

// box mask in .x, ctr mask in .y
__device__ ulonglong2 g_xtab[NB][NCOLS];
__device__ ulonglong2 g_ytab[NB][NROWS];

// ---------------- Kernel 1: per-(b, column/row) 50-bit masks ----------------
__global__ __launch_bounds__(352)
void build_tables_kernel(const float* __restrict__ labels) {
    __shared__ float4 sbox[NG];      // box {xlo, xhi, ylo, yhi}
    __shared__ float4 sctr[3][NG];   // ctr per level

    const int b   = blockIdx.x;
    const int tid = threadIdx.x;
    const float PINF = __int_as_float(0x7f800000);
    const float NINF = __int_as_float(0xff800000);

    if (tid < 3 * NG) {
        const int L = tid / NG;
        const int g = tid % NG;
        const float* lb = labels + ((size_t)b * NG + g) * 5;
        const float c  = lb[0];
        const float gx = lb[1];
        const float gy = lb[2];
        const float gw = lb[3];
        const float gh = lb[4];
        const bool valid = (c + gx + gy + gw + gh) > 0.0f;  // invalid rows are exactly 0
        if (L == 0) {
            const float hw = 0.5f * gw, hh = 0.5f * gh;
            sbox[g] = valid ? make_float4(gx - hw, gx + hw, gy - hh, gy + hh)
                            : make_float4(PINF, NINF, PINF, NINF);
        }
        const float r = (L == 0) ? 20.0f : (L == 1) ? 40.0f : 80.0f;  // 2.5*stride
        sctr[L][g] = valid ? make_float4(gx - r, gx + r, gy - r, gy + r)
                           : make_float4(PINF, NINF, PINF, NINF);
    }
    __syncthreads();

    const int e = tid;
    if (e < NCOLS) {
        int L, col; float s;
        if (e < 120)      { L = 0; col = e;        s = 8.0f;  }
        else if (e < 180) { L = 1; col = e - 120;  s = 16.0f; }
        else              { L = 2; col = e - 180;  s = 32.0f; }
        const float xc = ((float)col + 0.5f) * s;
        unsigned long long bb = 0ull, cc = 0ull;
#pragma unroll
        for (int g = 0; g < NG; ++g) {
            const float4 B = sbox[g];
            const float4 C = sctr[L][g];
            if (fminf(xc - B.x, B.y - xc) > 0.0f) bb |= (1ull << g);
            if (fminf(xc - C.x, C.y - xc) > 0.0f) cc |= (1ull << g);
        }
        g_xtab[b][e] = make_ulonglong2(bb, cc);
    } else if (e < NCOLS + NROWS) {
        const int e2 = e - NCOLS;
        int L, row; float s;
        if (e2 < 68)       { L = 0; row = e2;       s = 8.0f;  }
        else if (e2 < 102) { L = 1; row = e2 - 68;  s = 16.0f; }
        else               { L = 2; row = e2 - 102; s = 32.0f; }
        const float yc = ((float)row + 0.5f) * s;
        unsigned long long bb = 0ull, cc = 0ull;
#pragma unroll
        for (int g = 0; g < NG; ++g) {
            const float4 B = sbox[g];
            const float4 C = sctr[L][g];
            if (fminf(yc - B.z, B.w - yc) > 0.0f) bb |= (1ull << g);
            if (fminf(yc - C.z, C.w - yc) > 0.0f) cc |= (1ull << g);
        }
        g_ytab[b][e2] = make_ulonglong2(bb, cc);
    }
}

// ---------------- Kernel 2: decode + mask expansion (2 anchors/thread) -------
__device__ __forceinline__ float bit2f(unsigned int word, int g) {
    // ((word >> g) & 1) * 0x3f800000 reinterpreted as float -> 1.0f or 0.0f
    return __uint_as_float(((word >> g) & 1u) * 0x3f800000u);
}

__global__ __launch_bounds__(256)
void decode_mask_kernel(const float* __restrict__ preds,
                        float* __restrict__ out) {
    const int b   = blockIdx.y;
    const int t   = blockIdx.x * blockDim.x + threadIdx.x;
    const int a0  = t * 2;                      // even; pairs never cross levels/rows
    if (a0 >= A_TOTAL) return;

    int L, i, w; float s;
    if (a0 < A_L0)       { L = 0; i = a0;          w = 120; s = 8.0f;  }
    else if (a0 < A_L01) { L = 1; i = a0 - A_L0;   w = 60;  s = 16.0f; }
    else                 { L = 2; i = a0 - A_L01;  w = 30;  s = 32.0f; }
    const int row = i / w;
    const int col = i - row * w;                // even

    // ---- decode both anchors (contiguous 128B) ----
    {
        const float xg0 = (float)col, xg1 = (float)(col + 1);
        const float yg  = (float)row;
        const float4* p4 = reinterpret_cast<const float4*>(
            preds + ((size_t)b * A_TOTAL + a0) * NCH);
        float4* o4 = reinterpret_cast<float4*>(
            out + ((size_t)b * A_TOTAL + a0) * NCH);
        float4 v0 = p4[0];
        float4 u0 = p4[4];
        float4 r0, q0;
        r0.x = (v0.x + xg0) * s;
        r0.y = (v0.y + yg) * s;
        r0.z = __expf(v0.z) * s;
        r0.w = __expf(v0.w) * s;
        q0.x = (u0.x + xg1) * s;
        q0.y = (u0.y + yg) * s;
        q0.z = __expf(u0.z) * s;
        q0.w = __expf(u0.w) * s;
        o4[0] = r0;
        o4[1] = p4[1];
        o4[2] = p4[2];
        o4[3] = p4[3];
        o4[4] = q0;
        o4[5] = p4[5];
        o4[6] = p4[6];
        o4[7] = p4[7];
    }

    // ---- table lookups + 64-bit combines ----
    const int cbase = (L == 0) ? 0 : (L == 1) ? 120 : 180;
    const int rbase = (L == 0) ? 0 : (L == 1) ? 68  : 102;
    const ulonglong2 xe0 = g_xtab[b][cbase + col];
    const ulonglong2 xe1 = g_xtab[b][cbase + col + 1];
    const ulonglong2 ye  = g_ytab[b][rbase + row];

    const unsigned long long box0 = xe0.x & ye.x;
    const unsigned long long ctr0 = xe0.y & ye.y;
    const unsigned long long box1 = xe1.x & ye.x;
    const unsigned long long ctr1 = xe1.y & ye.y;
    const unsigned long long both0 = box0 & ctr0;
    const unsigned long long both1 = box1 & ctr1;

    float* out_fg  = out + (size_t)NB * A_TOTAL * NCH;
    float* out_ibc = out_fg + (size_t)NB * A_TOTAL;

    // fg = any(box | ctr); the reference's "& fg_mask" on ibc is redundant
    // because box&ctr != 0 implies box|ctr != 0.
    {
        const float f0 = ((box0 | ctr0) != 0ull) ? 1.0f : 0.0f;
        const float f1 = ((box1 | ctr1) != 0ull) ? 1.0f : 0.0f;
        float* pf = out_fg + (size_t)b * A_TOTAL + a0;   // even offset -> 8B aligned
        *reinterpret_cast<float2*>(pf) = make_float2(f0, f1);
    }

    // ---- expand 50 bits -> 50 float2 stores (stride A) ----
    const unsigned int lo0 = (unsigned int)both0, hi0 = (unsigned int)(both0 >> 32);
    const unsigned int lo1 = (unsigned int)both1, hi1 = (unsigned int)(both1 >> 32);
    float* pb = out_ibc + (size_t)b * NG * A_TOTAL + a0;  // even offset -> 8B aligned

#pragma unroll
    for (int g = 0; g < 32; ++g) {
        reinterpret_cast<float2*>(pb)[0] = make_float2(bit2f(lo0, g), bit2f(lo1, g));
        pb += A_TOTAL;
    }
#pragma unroll
    for (int g = 0; g < 18; ++g) {
        reinterpret_cast<float2*>(pb)[0] = make_float2(bit2f(hi0, g), bit2f(hi1, g));
        pb += A_TOTAL;
    }
}

extern "C" void kernel_launch(void* const* d_in, const int* in_sizes, int n_in,
                              void* d_out, int out_size) {
    const float* preds  = (const float*)d_in[0];
    const float* labels = (const float*)d_in[1];
    float* out = (float*)d_out;

    build_tables_kernel<<<NB, 352>>>(labels);

    const int pairs = A_TOTAL / 2;                    // 5355
    dim3 block(256);
    dim3 grid((pairs + 255) / 256, NB);               // 21 x 32
    decode_mask_kernel<<<grid, block>>>(preds, out);
}

// round 6
// speedup vs baseline: 1.3515x; 1.1878x over previous
#include <cuda_runtime.h>
#include <cuda_bf16.h>

// A = 8160 (68x120,s=8) + 2040 (34x60,s=16) + 510 (17x30,s=32) = 10710
// Output: [decoded B*A*16][fg B*A][ibc B*G*A], all f32.
//
// Separable-mask identity: in_box(a,g) = (x-margin>0) AND (y-margin>0);
// x depends only on column (210 distinct), y only on row (119 distinct).
// Tables of 50-bit masks per (b,col)/(b,row) -> per-anchor work is 64-bit ANDs.

#define A_TOTAL 10710
#define A_L0    8160
#define A_L01   10200
#define NB      32
#define NG      50
#define NCH     16

#define NCOLS   210
#define NROWS   119

#define MASK_ABLKS   42                       // ceil(10710/256)
#define MASK_BLOCKS  (MASK_ABLKS * NB)        // 1344
#define TOTF4        (NB * A_TOTAL * 4)       // 1370880 float4s in decoded
#define COPY_BLOCKS  ((TOTF4 + 511) / 512)    // 2678 (2 float4 per thread)

__device__ ulonglong2 g_xtab[NB][NCOLS];   // .x = box bits, .y = ctr bits
__device__ ulonglong2 g_ytab[NB][NROWS];

// ---------------- Kernel 1: per-(b, column/row) 50-bit masks ----------------
__global__ __launch_bounds__(352)
void build_tables_kernel(const float* __restrict__ labels) {
    __shared__ float4 sbox[NG];
    __shared__ float4 sctr[3][NG];

    const int b   = blockIdx.x;
    const int tid = threadIdx.x;
    const float PINF = __int_as_float(0x7f800000);
    const float NINF = __int_as_float(0xff800000);

    if (tid < 3 * NG) {
        const int L = tid / NG;
        const int g = tid % NG;
        const float* lb = labels + ((size_t)b * NG + g) * 5;
        const float c  = lb[0];
        const float gx = lb[1];
        const float gy = lb[2];
        const float gw = lb[3];
        const float gh = lb[4];
        const bool valid = (c + gx + gy + gw + gh) > 0.0f;  // invalid rows are exactly 0
        if (L == 0) {
            const float hw = 0.5f * gw, hh = 0.5f * gh;
            sbox[g] = valid ? make_float4(gx - hw, gx + hw, gy - hh, gy + hh)
                            : make_float4(PINF, NINF, PINF, NINF);
        }
        const float r = (L == 0) ? 20.0f : (L == 1) ? 40.0f : 80.0f;  // 2.5*stride
        sctr[L][g] = valid ? make_float4(gx - r, gx + r, gy - r, gy + r)
                           : make_float4(PINF, NINF, PINF, NINF);
    }
    __syncthreads();

    const int e = tid;
    if (e < NCOLS) {
        int L, col; float s;
        if (e < 120)      { L = 0; col = e;        s = 8.0f;  }
        else if (e < 180) { L = 1; col = e - 120;  s = 16.0f; }
        else              { L = 2; col = e - 180;  s = 32.0f; }
        const float xc = ((float)col + 0.5f) * s;
        unsigned long long bb = 0ull, cc = 0ull;
#pragma unroll
        for (int g = 0; g < NG; ++g) {
            const float4 B = sbox[g];
            const float4 C = sctr[L][g];
            if (fminf(xc - B.x, B.y - xc) > 0.0f) bb |= (1ull << g);
            if (fminf(xc - C.x, C.y - xc) > 0.0f) cc |= (1ull << g);
        }
        g_xtab[b][e] = make_ulonglong2(bb, cc);
    } else if (e < NCOLS + NROWS) {
        const int e2 = e - NCOLS;
        int L, row; float s;
        if (e2 < 68)       { L = 0; row = e2;       s = 8.0f;  }
        else if (e2 < 102) { L = 1; row = e2 - 68;  s = 16.0f; }
        else               { L = 2; row = e2 - 102; s = 32.0f; }
        const float yc = ((float)row + 0.5f) * s;
        unsigned long long bb = 0ull, cc = 0ull;
#pragma unroll
        for (int g = 0; g < NG; ++g) {
            const float4 B = sbox[g];
            const float4 C = sctr[L][g];
            if (fminf(yc - B.z, B.w - yc) > 0.0f) bb |= (1ull << g);
            if (fminf(yc - C.z, C.w - yc) > 0.0f) cc |= (1ull << g);
        }
        g_ytab[b][e2] = make_ulonglong2(bb, cc);
    }
}

// ---------------- Kernel 2: masks (blocks [0,1344)) + decode/copy ------------
__device__ __forceinline__ float bit2f(unsigned int word, int g) {
    return __uint_as_float(((word >> g) & 1u) * 0x3f800000u);
}

__device__ __forceinline__ void anchor_geom(int a, int& L, int& row, int& col, float& s) {
    int i, w;
    if (a < A_L0)       { L = 0; i = a;          w = 120; s = 8.0f;  }
    else if (a < A_L01) { L = 1; i = a - A_L0;   w = 60;  s = 16.0f; }
    else                { L = 2; i = a - A_L01;  w = 30;  s = 32.0f; }
    row = i / w;
    col = i - row * w;
}

__global__ __launch_bounds__(256)
void main_kernel(const float* __restrict__ preds,
                 float* __restrict__ out) {
    const int blk = blockIdx.x;
    const int tid = threadIdx.x;

    if (blk < MASK_BLOCKS) {
        // ================= mask role: one anchor per thread =================
        const int b = blk / MASK_ABLKS;
        const int a = (blk % MASK_ABLKS) * 256 + tid;
        if (a >= A_TOTAL) return;

        int L, row, col; float s;
        anchor_geom(a, L, row, col, s);

        const int cbase = (L == 0) ? 0 : (L == 1) ? 120 : 180;
        const int rbase = (L == 0) ? 0 : (L == 1) ? 68  : 102;
        const ulonglong2 xe = g_xtab[b][cbase + col];
        const ulonglong2 ye = g_ytab[b][rbase + row];

        const unsigned long long box  = xe.x & ye.x;
        const unsigned long long ctr  = xe.y & ye.y;
        const unsigned long long both = box & ctr;

        float* out_fg  = out + (size_t)NB * A_TOTAL * NCH;
        float* out_ibc = out_fg + (size_t)NB * A_TOTAL;

        // fg = any(box | ctr); "& fg" on ibc is redundant (both!=0 => fg).
        out_fg[(size_t)b * A_TOTAL + a] = ((box | ctr) != 0ull) ? 1.0f : 0.0f;

        const unsigned int lo = (unsigned int)both;
        const unsigned int hi = (unsigned int)(both >> 32);
        float* pb = out_ibc + (size_t)b * NG * A_TOTAL + a;
#pragma unroll
        for (int g = 0; g < 32; ++g) {
            *pb = bit2f(lo, g);
            pb += A_TOTAL;
        }
#pragma unroll
        for (int g = 0; g < 18; ++g) {
            *pb = bit2f(hi, g);
            pb += A_TOTAL;
        }
    } else {
        // ============ copy/decode role: coalesced float4 streaming ==========
        const int cb = blk - MASK_BLOCKS;
        const float4* __restrict__ p4 = reinterpret_cast<const float4*>(preds);
        float4* __restrict__ o4 = reinterpret_cast<float4*>(out);

#pragma unroll
        for (int it = 0; it < 2; ++it) {
            const int j = cb * 512 + it * 256 + tid;   // float4 index
            if (j >= TOTF4) break;
            float4 v = p4[j];
            if ((j & 3) == 0) {
                // this is channels 0..3 of anchor (j>>2) % A in batch (j>>2)/A
                const int alin = j >> 2;
                const int b = alin / A_TOTAL;
                const int a = alin - b * A_TOTAL;
                int L, row, col; float s;
                anchor_geom(a, L, row, col, s);
                float4 r;
                r.x = (v.x + (float)col) * s;
                r.y = (v.y + (float)row) * s;
                r.z = __expf(v.z) * s;
                r.w = __expf(v.w) * s;
                v = r;
            }
            o4[j] = v;
        }
    }
}

extern "C" void kernel_launch(void* const* d_in, const int* in_sizes, int n_in,
                              void* d_out, int out_size) {
    const float* preds  = (const float*)d_in[0];
    const float* labels = (const float*)d_in[1];
    float* out = (float*)d_out;

    build_tables_kernel<<<NB, 352>>>(labels);
    main_kernel<<<MASK_BLOCKS + COPY_BLOCKS, 256>>>(preds, out);
}

// round 8
// speedup vs baseline: 1.4844x; 1.0983x over previous
#include <cuda_runtime.h>
#include <cuda_bf16.h>

// A = 8160 (68x120,s=8) + 2040 (34x60,s=16) + 510 (17x30,s=32) = 10710
// Output: [decoded B*A*16][fg B*A][ibc B*G*A], all f32.
//
// Separable-mask identity: in_box(a,g) = (x-margin>0) AND (y-margin>0);
// x depends only on the anchor's column (210 distinct), y only on its row (119).
// Each mask block computes all 329 50-bit mask table entries in SHARED memory
// (cheap: ~130K flops), then per anchor the test is three 64-bit ANDs.
// Single kernel launch: blocks [0,672) do masks, [672,3350) stream decode/copy.

#define A_TOTAL 10710
#define A_L0    8160
#define A_L01   10200
#define NB      32
#define NG      50
#define NCH     16

#define NCOLS   210
#define NROWS   119
#define NENT    (NCOLS + NROWS)               // 329

#define MASK_PER_BLK 512                      // anchors per mask block (2/thread)
#define MASK_ABLKS   ((A_TOTAL + MASK_PER_BLK - 1) / MASK_PER_BLK)  // 21
#define MASK_BLOCKS  (MASK_ABLKS * NB)        // 672
#define TOTF4        (NB * A_TOTAL * 4)       // 1370880 float4s in decoded
#define COPY_BLOCKS  ((TOTF4 + 511) / 512)    // 2678 (2 float4 per thread)

__device__ __forceinline__ float bit2f(unsigned int word, int g) {
    return __uint_as_float(((word >> g) & 1u) * 0x3f800000u);
}

__device__ __forceinline__ void anchor_geom(int a, int& L, int& row, int& col, float& s) {
    int i, w;
    if (a < A_L0)       { L = 0; i = a;          w = 120; s = 8.0f;  }
    else if (a < A_L01) { L = 1; i = a - A_L0;   w = 60;  s = 16.0f; }
    else                { L = 2; i = a - A_L01;  w = 30;  s = 32.0f; }
    row = i / w;
    col = i - row * w;
}

__global__ __launch_bounds__(256)
void main_kernel(const float* __restrict__ preds,
                 const float* __restrict__ labels,
                 float* __restrict__ out) {
    __shared__ float4 sbox[NG];               // box {xlo,xhi,ylo,yhi}
    __shared__ float4 sctr[3][NG];            // ctr bounds per level
    __shared__ ulonglong2 sx[NCOLS];          // .x = box bits, .y = ctr bits
    __shared__ ulonglong2 sy[NROWS];

    const int blk = blockIdx.x;
    const int tid = threadIdx.x;

    if (blk >= MASK_BLOCKS) {
        // ============ copy/decode role: coalesced float4 streaming ==========
        const int cb = blk - MASK_BLOCKS;
        const float4* __restrict__ p4 = reinterpret_cast<const float4*>(preds);
        float4* __restrict__ o4 = reinterpret_cast<float4*>(out);
#pragma unroll
        for (int it = 0; it < 2; ++it) {
            const int j = cb * 512 + it * 256 + tid;   // float4 index
            if (j >= TOTF4) break;
            float4 v = p4[j];
            if ((j & 3) == 0) {                 // channels 0..3 of some anchor
                const int alin = j >> 2;
                const int b = alin / A_TOTAL;
                const int a = alin - b * A_TOTAL;
                int L, row, col; float s;
                anchor_geom(a, L, row, col, s);
                float4 r;
                r.x = (v.x + (float)col) * s;
                r.y = (v.y + (float)row) * s;
                r.z = __expf(v.z) * s;
                r.w = __expf(v.w) * s;
                v = r;
            }
            o4[j] = v;
        }
        return;
    }

    // ======================= mask role ======================================
    const int b    = blk / MASK_ABLKS;
    const int abase = (blk % MASK_ABLKS) * MASK_PER_BLK;

    const float PINF = __int_as_float(0x7f800000);
    const float NINF = __int_as_float(0xff800000);

    // Phase 1: label bounds into shared
    if (tid < 3 * NG) {
        const int L = tid / NG;
        const int g = tid % NG;
        const float* lb = labels + ((size_t)b * NG + g) * 5;
        const float c  = lb[0];
        const float gx = lb[1];
        const float gy = lb[2];
        const float gw = lb[3];
        const float gh = lb[4];
        const bool valid = (c + gx + gy + gw + gh) > 0.0f;  // invalid rows are exactly 0
        if (L == 0) {
            const float hw = 0.5f * gw, hh = 0.5f * gh;
            sbox[g] = valid ? make_float4(gx - hw, gx + hw, gy - hh, gy + hh)
                            : make_float4(PINF, NINF, PINF, NINF);
        }
        const float r = (L == 0) ? 20.0f : (L == 1) ? 40.0f : 80.0f;  // 2.5*stride
        sctr[L][g] = valid ? make_float4(gx - r, gx + r, gy - r, gy + r)
                           : make_float4(PINF, NINF, PINF, NINF);
    }
    __syncthreads();

    // Phase 2: all 329 table entries (2 passes of 256 threads)
#pragma unroll
    for (int pass = 0; pass < 2; ++pass) {
        const int e = pass * 256 + tid;
        if (e < NCOLS) {
            int L, col; float s;
            if (e < 120)      { L = 0; col = e;        s = 8.0f;  }
            else if (e < 180) { L = 1; col = e - 120;  s = 16.0f; }
            else              { L = 2; col = e - 180;  s = 32.0f; }
            const float xc = ((float)col + 0.5f) * s;
            unsigned long long bb = 0ull, cc = 0ull;
#pragma unroll
            for (int g = 0; g < NG; ++g) {
                const float4 B = sbox[g];
                const float4 C = sctr[L][g];
                if (fminf(xc - B.x, B.y - xc) > 0.0f) bb |= (1ull << g);
                if (fminf(xc - C.x, C.y - xc) > 0.0f) cc |= (1ull << g);
            }
            sx[e] = make_ulonglong2(bb, cc);
        } else if (e < NENT) {
            const int e2 = e - NCOLS;
            int L, row; float s;
            if (e2 < 68)       { L = 0; row = e2;       s = 8.0f;  }
            else if (e2 < 102) { L = 1; row = e2 - 68;  s = 16.0f; }
            else               { L = 2; row = e2 - 102; s = 32.0f; }
            const float yc = ((float)row + 0.5f) * s;
            unsigned long long bb = 0ull, cc = 0ull;
#pragma unroll
            for (int g = 0; g < NG; ++g) {
                const float4 B = sbox[g];
                const float4 C = sctr[L][g];
                if (fminf(yc - B.z, B.w - yc) > 0.0f) bb |= (1ull << g);
                if (fminf(yc - C.z, C.w - yc) > 0.0f) cc |= (1ull << g);
            }
            sy[e2] = make_ulonglong2(bb, cc);
        }
    }
    __syncthreads();

    // Phase 3: two anchors per thread (a0 even -> pair shares row & level)
    const int a0 = abase + tid * 2;
    if (a0 >= A_TOTAL) return;

    int L, row, col; float s;
    anchor_geom(a0, L, row, col, s);
    const int cbase = (L == 0) ? 0 : (L == 1) ? 120 : 180;
    const int rbase = (L == 0) ? 0 : (L == 1) ? 68  : 102;

    const ulonglong2 xe0 = sx[cbase + col];
    const ulonglong2 xe1 = sx[cbase + col + 1];
    const ulonglong2 ye  = sy[rbase + row];

    const unsigned long long box0 = xe0.x & ye.x;
    const unsigned long long ctr0 = xe0.y & ye.y;
    const unsigned long long box1 = xe1.x & ye.x;
    const unsigned long long ctr1 = xe1.y & ye.y;
    const unsigned long long both0 = box0 & ctr0;
    const unsigned long long both1 = box1 & ctr1;

    float* out_fg  = out + (size_t)NB * A_TOTAL * NCH;
    float* out_ibc = out_fg + (size_t)NB * A_TOTAL;

    // fg = any(box | ctr); "& fg" on ibc is redundant (both!=0 => fg true).
    {
        const float f0 = ((box0 | ctr0) != 0ull) ? 1.0f : 0.0f;
        const float f1 = ((box1 | ctr1) != 0ull) ? 1.0f : 0.0f;
        float* pf = out_fg + (size_t)b * A_TOTAL + a0;   // even -> 8B aligned
        *reinterpret_cast<float2*>(pf) = make_float2(f0, f1);
    }

    const unsigned int lo0 = (unsigned int)both0, hi0 = (unsigned int)(both0 >> 32);
    const unsigned int lo1 = (unsigned int)both1, hi1 = (unsigned int)(both1 >> 32);
    float* pb = out_ibc + (size_t)b * NG * A_TOTAL + a0; // even -> 8B aligned

#pragma unroll
    for (int g = 0; g < 32; ++g) {
        *reinterpret_cast<float2*>(pb) = make_float2(bit2f(lo0, g), bit2f(lo1, g));
        pb += A_TOTAL;
    }
#pragma unroll
    for (int g = 0; g < 18; ++g) {
        *reinterpret_cast<float2*>(pb) = make_float2(bit2f(hi0, g), bit2f(hi1, g));
        pb += A_TOTAL;
    }
}

extern "C" void kernel_launch(void* const* d_in, const int* in_sizes, int n_in,
                              void* d_out, int out_size) {
    const float* preds  = (const float*)d_in[0];
    const float* labels = (const float*)d_in[1];
    float* out = (float*)d_out;

    main_kernel<<<MASK_BLOCKS + COPY_BLOCKS, 256>>>(preds, labels, out);
}